// round 14
// baseline (speedup 1.0000x reference)
#include <cuda_runtime.h>
#include <cuda_fp16.h>

// Problem constants: B=32, C=3, H=W=512
#define Bv 32
#define Cv 3
#define Hv 512
#define Wv 512
#define PLANE (Hv*Wv)            // 262144
#define NPLANES (Bv*Cv)          // 96
#define K1_BLOCKS_PER_PLANE 32
#define RSTRIP 16                // output rows per K2 block (32 strips/plane)
#define PCHUNK 48                // planes per pipeline chunk

// Deterministic partial sums (no atomics): one slot per (plane, block)
__device__ float d_partial[NPLANES * K1_BLOCKS_PER_PLANE];
// fp16 scratch holding y = x^gamma for ONE chunk (24 MB, reused per chunk,
// stays L2-hot: written by K1(c), consumed by K2(c), overwritten by K1(c+1))
__device__ __half d_scratch[(size_t)PCHUNK * PLANE];

__device__ __forceinline__ float fast_pow(float x, float g) {
    return __powf(x, g);         // MUFU.LG2 + FMUL + MUFU.EX2 ; 0^g -> 0 correct
}

// ---------------- Kernel 1: per-plane sum of x^gamma + fp16 y scratch ----------------
// x reads are streaming (__ldcs): x is never re-read, keep it from displacing
// the scratch lines in L2. Scratch stores use default policy (L2-allocate).
__global__ void __launch_bounds__(256) k1_pow_sum(const float* __restrict__ x,
                                                 const float* __restrict__ gamma,
                                                 int plane0) {
    const int plane = plane0 + blockIdx.y;   // global plane b*3 + c
    const int b = plane / Cv;
    const float g = __ldg(&gamma[b]);
    const float4* px = (const float4*)(x + (size_t)plane * PLANE);
    uint2* pu = (uint2*)(d_scratch + (size_t)blockIdx.y * PLANE);  // local plane

    float s0 = 0.f, s1 = 0.f, s2 = 0.f, s3 = 0.f;
    int base = blockIdx.x * 2048 + threadIdx.x;   // 2048 float4 per block
#pragma unroll
    for (int k = 0; k < 8; k++) {
        int idx = base + k * 256;
        float4 v = __ldcs(px + idx);
        float y0 = fast_pow(v.x, g);
        float y1 = fast_pow(v.y, g);
        float y2 = fast_pow(v.z, g);
        float y3 = fast_pow(v.w, g);
        s0 += y0; s1 += y1; s2 += y2; s3 += y3;
        __half2 h01 = __floats2half2_rn(y0, y1);
        __half2 h23 = __floats2half2_rn(y2, y3);
        uint2 u;
        u.x = *reinterpret_cast<unsigned*>(&h01);
        u.y = *reinterpret_cast<unsigned*>(&h23);
        pu[idx] = u;
    }
    float s = (s0 + s1) + (s2 + s3);
#pragma unroll
    for (int o = 16; o; o >>= 1) s += __shfl_xor_sync(0xFFFFFFFFu, s, o);

    __shared__ float ws[8];
    int lane = threadIdx.x & 31, w = threadIdx.x >> 5;
    if (lane == 0) ws[w] = s;
    __syncthreads();
    if (w == 0) {
        s = (lane < 8) ? ws[lane] : 0.f;
#pragma unroll
        for (int o = 4; o; o >>= 1) s += __shfl_xor_sync(0xFFFFFFFFu, s, o);
        if (lane == 0) d_partial[plane * K1_BLOCKS_PER_PLANE + blockIdx.x] = s;
    }
}

// ---------------- Kernel 2 body: conv pipeline reading fp16 scratch ----------------
// Thread t owns output columns 4t..4t+3. Walks RSTRIP+2 scratch rows (8B/row
// per thread) with depth-2 prefetch; horizontal halo via shuffles + 2
// predicated scalar loads at warp edges. No pow, no MUFU. Scratch reads are
// last-use (__ldlu, dead after read); out stores stream (__stcs).
template <bool INTERIOR>
__device__ __forceinline__ void k2_body(const __half* __restrict__ psc,
                                        float* __restrict__ po,
                                        int y0, int tid, int lane,
                                        float wct, float beta, float s) {
    const int cbase = (tid >> 5) * 128;      // warp's first column
    const bool evL = (lane == 0)  && (cbase > 0);
    const bool evR = (lane == 31) && (cbase + 128 < Wv);
    const int eoff = evL ? (cbase - 1) : (cbase + 128);
    const bool ev  = evL || evR;

    float rs0[4] = {0.f, 0.f, 0.f, 0.f};
    float rs1[4] = {0.f, 0.f, 0.f, 0.f};
    float ctr[4] = {0.f, 0.f, 0.f, 0.f};

    uint2 vbuf[2];
    float ebuf[2];

    // Prologue: prefetch rows y0-1 and y0
#pragma unroll
    for (int k = 0; k < 2; k++) {
        int gy = y0 - 1 + k;
        vbuf[k] = make_uint2(0u, 0u);
        ebuf[k] = 0.f;
        if (INTERIOR || (unsigned)gy < (unsigned)Hv) {
            vbuf[k] = __ldlu(((const uint2*)(psc + gy * Wv)) + tid);
            if (ev) ebuf[k] = __half2float(__ldlu(psc + gy * Wv + eoff));
        }
    }

#pragma unroll
    for (int i = 0; i < RSTRIP + 2; i++) {
        const int gy = y0 - 1 + i;
        uint2 rv = vbuf[i & 1];
        float eyv = ebuf[i & 1];

        // Prefetch row gy+2 into the slot just freed
        if (i < RSTRIP) {
            const int gy2 = gy + 2;
            uint2 vp = make_uint2(0u, 0u);
            float ep = 0.f;
            if (INTERIOR || gy2 < Hv) {
                vp = __ldlu(((const uint2*)(psc + gy2 * Wv)) + tid);
                if (ev) ep = __half2float(__ldlu(psc + gy2 * Wv + eoff));
            }
            vbuf[i & 1] = vp;
            ebuf[i & 1] = ep;
        }

        // Unpack fp16 y and transform: f = sat(y*wct + beta) -> FFMA.SAT
        __half2 h01 = *reinterpret_cast<__half2*>(&rv.x);
        __half2 h23 = *reinterpret_cast<__half2*>(&rv.y);
        float2 f01 = __half22float2(h01);
        float2 f23 = __half22float2(h23);
        float f0 = __saturatef(fmaf(f01.x, wct, beta));
        float f1 = __saturatef(fmaf(f01.y, wct, beta));
        float f2 = __saturatef(fmaf(f23.x, wct, beta));
        float f3 = __saturatef(fmaf(f23.y, wct, beta));
        float e  = __saturatef(fmaf(eyv,  wct, beta));
        if (!INTERIOR) {
            const bool vval = (unsigned)gy < (unsigned)Hv;
            if (!vval) { f0 = f1 = f2 = f3 = 0.f; }
            if (!(vval && ev)) e = 0.f;
        } else {
            if (!ev) e = 0.f;
        }

        // Horizontal neighbors via shuffle (warp edges use e)
        float fl = __shfl_up_sync(0xFFFFFFFFu, f3, 1);
        if (lane == 0) fl = e;
        float fr = __shfl_down_sync(0xFFFFFFFFu, f0, 1);
        if (lane == 31) fr = e;

        float rs2_0 = fl + f0 + f1;
        float rs2_1 = f0 + f1 + f2;
        float rs2_2 = f1 + f2 + f3;
        float rs2_3 = f2 + f3 + fr;

        // Emit output row gy-1: out = sat(s*(9c - s9) + c)
        if (i >= 2) {
            float4 o4;
            float s9, c;

            c = ctr[0]; s9 = rs0[0] + rs1[0] + rs2_0;
            o4.x = __saturatef(fmaf(s, fmaf(9.f, c, -s9), c));

            c = ctr[1]; s9 = rs0[1] + rs1[1] + rs2_1;
            o4.y = __saturatef(fmaf(s, fmaf(9.f, c, -s9), c));

            c = ctr[2]; s9 = rs0[2] + rs1[2] + rs2_2;
            o4.z = __saturatef(fmaf(s, fmaf(9.f, c, -s9), c));

            c = ctr[3]; s9 = rs0[3] + rs1[3] + rs2_3;
            o4.w = __saturatef(fmaf(s, fmaf(9.f, c, -s9), c));

            __stcs(((float4*)(po + (gy - 1) * Wv)) + tid, o4);
        }

        // Rotate pipeline registers (renamed away by the full unroll)
        rs0[0] = rs1[0]; rs0[1] = rs1[1]; rs0[2] = rs1[2]; rs0[3] = rs1[3];
        rs1[0] = rs2_0;  rs1[1] = rs2_1;  rs1[2] = rs2_2;  rs1[3] = rs2_3;
        ctr[0] = f0; ctr[1] = f1; ctr[2] = f2; ctr[3] = f3;
    }
}

__global__ void __launch_bounds__(128) k2_main(const float* __restrict__ wb,
                                               const float* __restrict__ contrast,
                                               const float* __restrict__ sharpen,
                                               float* __restrict__ out,
                                               int plane0) {
    const int plane = plane0 + blockIdx.y;   // global plane
    const int b = plane / Cv;
    const float w  = __ldg(&wb[plane]);      // wb[b][c] flattens to wb[plane]
    const float ct = __ldg(&contrast[b]);
    const float s  = __ldg(&sharpen[b]);
    const float wct = w * ct;                // fold wb into contrast scale

    __shared__ float s_beta;
    const int tid  = threadIdx.x;
    const int lane = tid & 31;

    // Fold per-plane partials: warp 0, one load + shfl reduce.
    if (tid < 32) {
        float p = d_partial[plane * K1_BLOCKS_PER_PLANE + tid];
#pragma unroll
        for (int o = 16; o; o >>= 1) p += __shfl_xor_sync(0xFFFFFFFFu, p, o);
        if (tid == 0) {
            float mean = p * w * (1.0f / (float)PLANE);
            s_beta = mean - mean * ct;       // mean*(1-contrast)
        }
    }
    __syncthreads();
    const float beta = s_beta;

    const __half* __restrict__ psc = d_scratch + (size_t)blockIdx.y * PLANE;
    float* __restrict__ po = out + (size_t)plane * PLANE;
    const int y0 = blockIdx.x * RSTRIP;

    if (y0 >= RSTRIP && y0 + RSTRIP < Hv)
        k2_body<true>(psc, po, y0, tid, lane, wct, beta, s);
    else
        k2_body<false>(psc, po, y0, tid, lane, wct, beta, s);
}

extern "C" void kernel_launch(void* const* d_in, const int* in_sizes, int n_in,
                              void* d_out, int out_size) {
    const float* x        = (const float*)d_in[0];
    const float* gamma    = (const float*)d_in[1];
    const float* wb       = (const float*)d_in[2];
    const float* contrast = (const float*)d_in[3];
    const float* sharpen  = (const float*)d_in[4];
    float* out = (float*)d_out;

    // Pipeline by plane chunks: K1(c) computes sums AND fills the fp16 y
    // scratch; K2(c) consumes it while it is L2-hot. Same-stream ordering
    // guarantees K2(c) finishes before K1(c+1) overwrites the scratch.
    for (int p0 = 0; p0 < NPLANES; p0 += PCHUNK) {
        dim3 g1(K1_BLOCKS_PER_PLANE, PCHUNK);
        k1_pow_sum<<<g1, 256>>>(x, gamma, p0);
        dim3 g2(Hv / RSTRIP, PCHUNK);        // 32 strips x 48 planes = 1536 blocks
        k2_main<<<g2, 128>>>(wb, contrast, sharpen, out, p0);
    }
}

// round 15
// speedup vs baseline: 1.1670x; 1.1670x over previous
#include <cuda_runtime.h>
#include <cuda_fp16.h>

// Problem constants: B=32, C=3, H=W=512
#define Bv 32
#define Cv 3
#define Hv 512
#define Wv 512
#define PLANE (Hv*Wv)            // 262144
#define NPLANES (Bv*Cv)          // 96
#define K1_BLOCKS_PER_PLANE 32
#define RSTRIP 8                 // output rows per K2 block (64 strips/plane)
#define PCHUNK 48                // planes per pipeline chunk
#define PFD 3                    // K2 prefetch depth (rows in flight)

// Deterministic partial sums (no atomics): one slot per (plane, block)
__device__ float d_partial[NPLANES * K1_BLOCKS_PER_PLANE];
// fp16 scratch holding y = x^gamma for ONE chunk (24 MB, reused per chunk,
// stays L2-hot: written by K1(c), consumed by K2(c), overwritten by K1(c+1))
__device__ __half d_scratch[(size_t)PCHUNK * PLANE];

__device__ __forceinline__ float fast_pow(float x, float g) {
    return __powf(x, g);         // MUFU.LG2 + FMUL + MUFU.EX2 ; 0^g -> 0 correct
}

// ---------------- Kernel 1: per-plane sum of x^gamma + fp16 y scratch ----------------
__global__ void __launch_bounds__(256) k1_pow_sum(const float* __restrict__ x,
                                                 const float* __restrict__ gamma,
                                                 int plane0) {
    const int plane = plane0 + blockIdx.y;   // global plane b*3 + c
    const int b = plane / Cv;
    const float g = __ldg(&gamma[b]);
    const float4* px = (const float4*)(x + (size_t)plane * PLANE);
    uint2* pu = (uint2*)(d_scratch + (size_t)blockIdx.y * PLANE);  // local plane

    float s0 = 0.f, s1 = 0.f, s2 = 0.f, s3 = 0.f;
    int base = blockIdx.x * 2048 + threadIdx.x;   // 2048 float4 per block
#pragma unroll
    for (int k = 0; k < 8; k++) {
        int idx = base + k * 256;
        float4 v = px[idx];
        float y0 = fast_pow(v.x, g);
        float y1 = fast_pow(v.y, g);
        float y2 = fast_pow(v.z, g);
        float y3 = fast_pow(v.w, g);
        s0 += y0; s1 += y1; s2 += y2; s3 += y3;
        __half2 h01 = __floats2half2_rn(y0, y1);
        __half2 h23 = __floats2half2_rn(y2, y3);
        uint2 u;
        u.x = *reinterpret_cast<unsigned*>(&h01);
        u.y = *reinterpret_cast<unsigned*>(&h23);
        pu[idx] = u;
    }
    float s = (s0 + s1) + (s2 + s3);
#pragma unroll
    for (int o = 16; o; o >>= 1) s += __shfl_xor_sync(0xFFFFFFFFu, s, o);

    __shared__ float ws[8];
    int lane = threadIdx.x & 31, w = threadIdx.x >> 5;
    if (lane == 0) ws[w] = s;
    __syncthreads();
    if (w == 0) {
        s = (lane < 8) ? ws[lane] : 0.f;
#pragma unroll
        for (int o = 4; o; o >>= 1) s += __shfl_xor_sync(0xFFFFFFFFu, s, o);
        if (lane == 0) d_partial[plane * K1_BLOCKS_PER_PLANE + blockIdx.x] = s;
    }
}

// ---------------- Kernel 2 body: conv pipeline reading fp16 scratch ----------------
// Thread t owns output columns 4t..4t+3. Walks RSTRIP+2 scratch rows (8B/row
// per thread) with depth-PFD prefetch; horizontal halo via shuffles + 2
// predicated scalar loads at warp edges. No pow, no MUFU. Scratch reads use
// DEFAULT policy (each line is read twice: interior + neighbor-strip halo);
// out stores stream (__stcs).
template <bool INTERIOR>
__device__ __forceinline__ void k2_body(const __half* __restrict__ psc,
                                        float* __restrict__ po,
                                        int y0, int tid, int lane,
                                        float wct, float beta, float s) {
    const int cbase = (tid >> 5) * 128;      // warp's first column
    const bool evL = (lane == 0)  && (cbase > 0);
    const bool evR = (lane == 31) && (cbase + 128 < Wv);
    const int eoff = evL ? (cbase - 1) : (cbase + 128);
    const bool ev  = evL || evR;

    float rs0[4] = {0.f, 0.f, 0.f, 0.f};
    float rs1[4] = {0.f, 0.f, 0.f, 0.f};
    float ctr[4] = {0.f, 0.f, 0.f, 0.f};

    uint2 vbuf[PFD];
    float ebuf[PFD];

    // Prologue: prefetch rows y0-1 .. y0-1+PFD-1
#pragma unroll
    for (int k = 0; k < PFD; k++) {
        int gy = y0 - 1 + k;
        vbuf[k] = make_uint2(0u, 0u);
        ebuf[k] = 0.f;
        if ((INTERIOR || (unsigned)gy < (unsigned)Hv) && k < RSTRIP + 2) {
            vbuf[k] = ((const uint2*)(psc + gy * Wv))[tid];
            if (ev) ebuf[k] = __half2float(psc[gy * Wv + eoff]);
        }
    }

#pragma unroll
    for (int i = 0; i < RSTRIP + 2; i++) {
        const int gy = y0 - 1 + i;
        uint2 rv = vbuf[i % PFD];
        float eyv = ebuf[i % PFD];

        // Prefetch row gy+PFD into the slot just freed
        if (i + PFD < RSTRIP + 2) {
            const int gyp = gy + PFD;
            uint2 vp = make_uint2(0u, 0u);
            float ep = 0.f;
            if (INTERIOR || gyp < Hv) {
                vp = ((const uint2*)(psc + gyp * Wv))[tid];
                if (ev) ep = __half2float(psc[gyp * Wv + eoff]);
            }
            vbuf[i % PFD] = vp;
            ebuf[i % PFD] = ep;
        }

        // Unpack fp16 y and transform: f = sat(y*wct + beta) -> FFMA.SAT
        __half2 h01 = *reinterpret_cast<__half2*>(&rv.x);
        __half2 h23 = *reinterpret_cast<__half2*>(&rv.y);
        float2 f01 = __half22float2(h01);
        float2 f23 = __half22float2(h23);
        float f0 = __saturatef(fmaf(f01.x, wct, beta));
        float f1 = __saturatef(fmaf(f01.y, wct, beta));
        float f2 = __saturatef(fmaf(f23.x, wct, beta));
        float f3 = __saturatef(fmaf(f23.y, wct, beta));
        float e  = __saturatef(fmaf(eyv,  wct, beta));
        if (!INTERIOR) {
            const bool vval = (unsigned)gy < (unsigned)Hv;
            if (!vval) { f0 = f1 = f2 = f3 = 0.f; }
            if (!(vval && ev)) e = 0.f;
        } else {
            if (!ev) e = 0.f;
        }

        // Horizontal neighbors via shuffle (warp edges use e)
        float fl = __shfl_up_sync(0xFFFFFFFFu, f3, 1);
        if (lane == 0) fl = e;
        float fr = __shfl_down_sync(0xFFFFFFFFu, f0, 1);
        if (lane == 31) fr = e;

        float rs2_0 = fl + f0 + f1;
        float rs2_1 = f0 + f1 + f2;
        float rs2_2 = f1 + f2 + f3;
        float rs2_3 = f2 + f3 + fr;

        // Emit output row gy-1: out = sat(s*(9c - s9) + c)
        if (i >= 2) {
            float4 o4;
            float s9, c;

            c = ctr[0]; s9 = rs0[0] + rs1[0] + rs2_0;
            o4.x = __saturatef(fmaf(s, fmaf(9.f, c, -s9), c));

            c = ctr[1]; s9 = rs0[1] + rs1[1] + rs2_1;
            o4.y = __saturatef(fmaf(s, fmaf(9.f, c, -s9), c));

            c = ctr[2]; s9 = rs0[2] + rs1[2] + rs2_2;
            o4.z = __saturatef(fmaf(s, fmaf(9.f, c, -s9), c));

            c = ctr[3]; s9 = rs0[3] + rs1[3] + rs2_3;
            o4.w = __saturatef(fmaf(s, fmaf(9.f, c, -s9), c));

            __stcs(((float4*)(po + (gy - 1) * Wv)) + tid, o4);
        }

        // Rotate pipeline registers (renamed away by the full unroll)
        rs0[0] = rs1[0]; rs0[1] = rs1[1]; rs0[2] = rs1[2]; rs0[3] = rs1[3];
        rs1[0] = rs2_0;  rs1[1] = rs2_1;  rs1[2] = rs2_2;  rs1[3] = rs2_3;
        ctr[0] = f0; ctr[1] = f1; ctr[2] = f2; ctr[3] = f3;
    }
}

__global__ void __launch_bounds__(128) k2_main(const float* __restrict__ wb,
                                               const float* __restrict__ contrast,
                                               const float* __restrict__ sharpen,
                                               float* __restrict__ out,
                                               int plane0) {
    const int plane = plane0 + blockIdx.y;   // global plane
    const int b = plane / Cv;
    const float w  = __ldg(&wb[plane]);      // wb[b][c] flattens to wb[plane]
    const float ct = __ldg(&contrast[b]);
    const float s  = __ldg(&sharpen[b]);
    const float wct = w * ct;                // fold wb into contrast scale

    __shared__ float s_beta;
    const int tid  = threadIdx.x;
    const int lane = tid & 31;

    // Fold per-plane partials: warp 0, one load + shfl reduce.
    if (tid < 32) {
        float p = d_partial[plane * K1_BLOCKS_PER_PLANE + tid];
#pragma unroll
        for (int o = 16; o; o >>= 1) p += __shfl_xor_sync(0xFFFFFFFFu, p, o);
        if (tid == 0) {
            float mean = p * w * (1.0f / (float)PLANE);
            s_beta = mean - mean * ct;       // mean*(1-contrast)
        }
    }
    __syncthreads();
    const float beta = s_beta;

    const __half* __restrict__ psc = d_scratch + (size_t)blockIdx.y * PLANE;
    float* __restrict__ po = out + (size_t)plane * PLANE;
    const int y0 = blockIdx.x * RSTRIP;

    if (y0 >= RSTRIP && y0 + RSTRIP < Hv)
        k2_body<true>(psc, po, y0, tid, lane, wct, beta, s);
    else
        k2_body<false>(psc, po, y0, tid, lane, wct, beta, s);
}

extern "C" void kernel_launch(void* const* d_in, const int* in_sizes, int n_in,
                              void* d_out, int out_size) {
    const float* x        = (const float*)d_in[0];
    const float* gamma    = (const float*)d_in[1];
    const float* wb       = (const float*)d_in[2];
    const float* contrast = (const float*)d_in[3];
    const float* sharpen  = (const float*)d_in[4];
    float* out = (float*)d_out;

    // Pipeline by plane chunks: K1(c) computes sums AND fills the fp16 y
    // scratch; K2(c) consumes it while it is L2-hot. Same-stream ordering
    // guarantees K2(c) finishes before K1(c+1) overwrites the scratch.
    for (int p0 = 0; p0 < NPLANES; p0 += PCHUNK) {
        dim3 g1(K1_BLOCKS_PER_PLANE, PCHUNK);
        k1_pow_sum<<<g1, 256>>>(x, gamma, p0);
        dim3 g2(Hv / RSTRIP, PCHUNK);        // 64 strips x 48 planes = 3072 blocks
        k2_main<<<g2, 128>>>(wb, contrast, sharpen, out, p0);
    }
}